// round 9
// baseline (speedup 1.0000x reference)
#include <cuda_runtime.h>

namespace {
constexpr int N_COLS = 8192;
constexpr int W_MAX  = 15;     // widths w = 2..15
constexpr int NW     = 14;
constexpr int HALO   = 14;     // W_MAX - 1
constexpr int TPB    = 128;    // 4 warps
constexpr int K_TOK  = 16;     // tokens per lane
constexpr int WTOK   = 32 * K_TOK;         // 512 tokens per warp
constexpr int TILE   = (TPB / 32) * WTOK;  // 2048 tokens per CTA
constexpr float NEGV = -1.0e9f;
constexpr unsigned FULL = 0xffffffffu;
}

__global__ __launch_bounds__(TPB, 6) void span_boost_kernel(
    const float* __restrict__ scores,
    const int*   __restrict__ mask,
    const float* __restrict__ gamma_p,
    const float* __restrict__ wlog,
    float*       __restrict__ out)
{
    const float NINF = __int_as_float(0xff800000);
    const int tid  = threadIdx.x;
    const int lane = tid & 31;
    const int wid  = tid >> 5;
    const int row  = blockIdx.y;
    const float* srow = scores + (size_t)row * N_COLS;
    const int*   mrow = mask   + (size_t)row * N_COLS;

    const int wb = blockIdx.x * TILE + wid * WTOK;  // warp token base
    const int t0 = wb + lane * K_TOK;               // lane token base

    // ---- lane-parallel softmax: ww[j] = weight of width j+2 ----
    float ww[NW];
    {
        float lg = (lane < W_MAX) ? __ldg(wlog + lane) : NINF;
        float mx = lg;
        #pragma unroll
        for (int o = 16; o >= 1; o >>= 1)
            mx = fmaxf(mx, __shfl_xor_sync(FULL, mx, o));
        float e = (lane < W_MAX) ? __expf(lg - mx) : 0.f;
        float s = e;
        #pragma unroll
        for (int o = 16; o >= 1; o >>= 1)
            s += __shfl_xor_sync(FULL, s, o);
        float wwv = __fdividef(e, s);
        #pragma unroll
        for (int j = 0; j < NW; j++)
            ww[j] = __shfl_sync(FULL, wwv, j + 1);
    }

    // ---- own masked values r[0..15] (direct LDG.128, always in-row) ----
    float r[30];
    #pragma unroll
    for (int q = 0; q < 4; q++) {
        int g = t0 + 4 * q;
        float4 s4 = *reinterpret_cast<const float4*>(srow + g);
        int4   m4 = *reinterpret_cast<const int4*>(mrow + g);
        r[4*q+0] = (m4.x == 0) ? NEGV : s4.x;
        r[4*q+1] = (m4.y == 0) ? NEGV : s4.y;
        r[4*q+2] = (m4.z == 0) ? NEGV : s4.z;
        r[4*q+3] = (m4.w == 0) ? NEGV : s4.w;
    }
    // right halo r[16..29]: neighbor lane's r[0..13] via shuffle
    #pragma unroll
    for (int k = 0; k < HALO; k++)
        r[16 + k] = __shfl_down_sync(FULL, r[k], 1);
    if (lane == 31) {                      // last lane loads real right halo
        #pragma unroll
        for (int q = 0; q < 4; q++) {
            int g = t0 + 16 + 4 * q;
            float v[4] = {NINF, NINF, NINF, NINF};
            if (g < N_COLS) {
                float4 s4 = *reinterpret_cast<const float4*>(srow + g);
                int4   m4 = *reinterpret_cast<const int4*>(mrow + g);
                v[0] = (m4.x == 0) ? NEGV : s4.x;
                v[1] = (m4.y == 0) ? NEGV : s4.y;
                v[2] = (m4.z == 0) ? NEGV : s4.z;
                v[3] = (m4.w == 0) ? NEGV : s4.w;
            }
            #pragma unroll
            for (int c = 0; c < 4; c++)
                if (16 + 4 * q + c < 30) r[16 + 4 * q + c] = v[c];
        }
    }

    // ---- warp-left halo: lanes 0..13 own start wb-14+lane; atomics-free ----
    float acc = NINF;                      // halo boost for token (wb + lane)
    {
        const bool hl = lane < HALO;
        float hv[W_MAX];
        #pragma unroll
        for (int k = 0; k < W_MAX; k++) {
            int g = wb - HALO + lane + k;
            float v = NINF;
            if (hl && g >= 0)
                v = (mrow[g] == 0) ? NEGV : srow[g];
            hv[k] = v;
        }
        float hw[NW];
        float m = fminf(hv[0], hv[1]);
        hw[0] = ww[0] * m;
        #pragma unroll
        for (int w = 3; w <= W_MAX; w++) {
            m = fminf(m, hv[w - 1]);
            hw[w - 2] = ww[w - 2] * m;
        }
        float Gv[16];                      // Gv[d] = max_{w>=d} hw; d = 1..15
        Gv[15] = hw[13];
        #pragma unroll
        for (int d = 14; d >= 2; d--) Gv[d] = fmaxf(Gv[d + 1], hw[d - 2]);
        Gv[1] = Gv[2];
        // token i receives lane (i+k)'s Gv[15-k]  (depth d = 15-k)
        #pragma unroll
        for (int k = 0; k < HALO; k++) {
            float v = __shfl_down_sync(FULL, Gv[15 - k], k);
            if (lane + k < HALO) acc = fmaxf(acc, v);
        }
    }

    float boost[K_TOK + HALO];             // local token slots 0..29

    // ---- 16 starts, descending; streamed shuffle handoff lane->lane+1 ----
    #pragma unroll
    for (int jj = 0; jj < K_TOK; jj++) {
        const int j = K_TOK - 1 - jj;      // 15 .. 0
        float h[NW];
        float m = fminf(r[j], r[j + 1]);
        h[0] = ww[0] * m;
        #pragma unroll
        for (int w = 3; w <= W_MAX; w++) {
            m = fminf(m, r[j + w - 1]);
            h[w - 2] = ww[w - 2] * m;
        }
        float g = h[NW - 1];                                // d = 15
        if (j == K_TOK - 1) boost[j + 14] = g;
        else                boost[j + 14] = fmaxf(boost[j + 14], g);
        #pragma unroll
        for (int d = W_MAX - 1; d >= 2; d--) {              // d = 14..2
            g = fmaxf(g, h[d - 2]);
            if (j == K_TOK - 1) boost[j + d - 1] = g;
            else                boost[j + d - 1] = fmaxf(boost[j + d - 1], g);
        }
        if (j >= K_TOK - 2) boost[j] = g;                   // d = 1: slots 14,15
        else                boost[j] = fmaxf(boost[j], g);  // incoming landed first
        if (j >= 2) {                                       // handoff slot j-2
            float tin = __shfl_up_sync(FULL, boost[j + 14], 1);
            boost[j - 2] = (lane == 0) ? NINF : tin;
        }
    }

    // ---- fold halo boosts into lane 0's tokens 0..13 ----
    #pragma unroll
    for (int i = 0; i < HALO; i++) {
        float v = __shfl_sync(FULL, acc, i);
        if (lane == 0) boost[i] = fmaxf(boost[i], v);
    }

    // ---- epilogue: out = score + gamma * max(boost, masked) ----
    const float gamma = *gamma_p;
    float* orow = out + (size_t)row * N_COLS;
    #pragma unroll
    for (int q = 0; q < K_TOK / 4; q++) {
        float4 s4 = *reinterpret_cast<const float4*>(&srow[t0 + 4 * q]);
        float4 o;
        o.x = s4.x + gamma * fmaxf(boost[4*q+0], r[4*q+0]);
        o.y = s4.y + gamma * fmaxf(boost[4*q+1], r[4*q+1]);
        o.z = s4.z + gamma * fmaxf(boost[4*q+2], r[4*q+2]);
        o.w = s4.w + gamma * fmaxf(boost[4*q+3], r[4*q+3]);
        *reinterpret_cast<float4*>(&orow[t0 + 4 * q]) = o;
    }
}

extern "C" void kernel_launch(void* const* d_in, const int* in_sizes, int n_in,
                              void* d_out, int out_size)
{
    const float* scores = (const float*)d_in[0];
    const int*   mask   = (const int*)d_in[1];
    const float* gamma  = (const float*)d_in[2];
    const float* wlog   = (const float*)d_in[3];
    float* out = (float*)d_out;
    const int B = in_sizes[0] / N_COLS;   // 512
    dim3 grid(N_COLS / TILE, B);          // (4, 512)
    span_boost_kernel<<<grid, TPB>>>(scores, mask, gamma, wlog, out);
}

// round 10
// speedup vs baseline: 1.1045x; 1.1045x over previous
#include <cuda_runtime.h>
#include <cuda_fp16.h>

namespace {
constexpr int N_COLS = 8192;
constexpr int W_MAX  = 15;     // widths w = 2..15
constexpr int NW     = 14;
constexpr int HALO   = 14;     // W_MAX - 1
constexpr int TPB    = 128;
constexpr int K_TOK  = 16;     // tokens per thread PER SEGMENT
constexpr int SEG    = TPB * K_TOK;   // 2048
constexpr int TILE   = 2 * SEG;       // 4096 tokens per CTA (2 segments)
constexpr float SENT = -60000.0f;     // fp16-exact sentinel (mask / row pad)
constexpr float NEGV = -1.0e9f;
constexpr unsigned FULL = 0xffffffffu;
constexpr unsigned KEY_NINF = 0x007fffffu; // fkey(-inf)
}

// order-preserving float<->uint key (total order incl. -inf)
__device__ __forceinline__ unsigned fkey(float f) {
    int u = __float_as_int(f);
    return (u >= 0) ? ((unsigned)u | 0x80000000u) : ~(unsigned)u;
}
__device__ __forceinline__ float funkey(unsigned k) {
    unsigned u = (k & 0x80000000u) ? (k & 0x7fffffffu) : ~k;
    return __int_as_float((int)u);
}
__device__ __forceinline__ __half2 shdn1(__half2 v) {  // lane+1's value
    unsigned u = *reinterpret_cast<unsigned*>(&v);
    u = __shfl_down_sync(FULL, u, 1);
    return *reinterpret_cast<__half2*>(&u);
}

__global__ __launch_bounds__(TPB, 5) void span_boost_kernel(
    const float* __restrict__ scores,
    const int*   __restrict__ mask,
    const float* __restrict__ gamma_p,
    const float* __restrict__ wlog,
    float*       __restrict__ out)
{
    __shared__ float    sww[NW];
    __shared__ unsigned xb[HALO];          // CTA-left-halo boost (fp32 keyed)
    __shared__ __half2  tailbuf[TPB][15];  // 14 used; stride 15 words

    const int tid  = threadIdx.x;
    const int row  = blockIdx.y;
    const int col0 = blockIdx.x * TILE;
    const float* srow = scores + (size_t)row * N_COLS;
    const int*   mrow = mask   + (size_t)row * N_COLS;

    if (tid < HALO) xb[tid] = KEY_NINF;
    if (tid == 0) {  // softmax over 15 width logits (fp32)
        float mx = wlog[0];
        #pragma unroll
        for (int j = 1; j < W_MAX; j++) mx = fmaxf(mx, wlog[j]);
        float e[W_MAX], ssum = 0.f;
        #pragma unroll
        for (int j = 0; j < W_MAX; j++) { e[j] = expf(wlog[j] - mx); ssum += e[j]; }
        float inv = 1.f / ssum;
        #pragma unroll
        for (int j = 0; j < NW; j++) sww[j] = e[j + 1] * inv;  // widths 2..15
    }
    __syncthreads();

    // packed weights + sentinel-class constant c = -1e9 * min_w ww_w
    __half2 ww2[NW];
    float wmin;
    {
        float w0 = sww[0]; wmin = w0; ww2[0] = __float2half2_rn(w0);
        #pragma unroll
        for (int j = 1; j < NW; j++) {
            float wj = sww[j];
            wmin = fminf(wmin, wj);
            ww2[j] = __float2half2_rn(wj);
        }
    }
    const float cfix = NEGV * wmin;

    // ---- own tokens, both segments, packed: r[k] = {segA[k], segB[k]} ----
    const int t0 = col0 + tid * K_TOK;     // segA base; segB = t0 + SEG
    __half2 r[30];
    #pragma unroll
    for (int q = 0; q < 4; q++) {
        int ga = t0 + 4 * q, gb = ga + SEG;
        float4 sa = *reinterpret_cast<const float4*>(srow + ga);
        int4   ma = *reinterpret_cast<const int4*>(mrow + ga);
        float4 sb = *reinterpret_cast<const float4*>(srow + gb);
        int4   mb = *reinterpret_cast<const int4*>(mrow + gb);
        r[4*q+0] = __floats2half2_rn(ma.x == 0 ? SENT : sa.x, mb.x == 0 ? SENT : sb.x);
        r[4*q+1] = __floats2half2_rn(ma.y == 0 ? SENT : sa.y, mb.y == 0 ? SENT : sb.y);
        r[4*q+2] = __floats2half2_rn(ma.z == 0 ? SENT : sa.z, mb.z == 0 ? SENT : sb.z);
        r[4*q+3] = __floats2half2_rn(ma.w == 0 ? SENT : sa.w, mb.w == 0 ? SENT : sb.w);
    }
    // right halo r[16..29] from lane+1 via shuffle (covers both segments)
    #pragma unroll
    for (int k = 0; k < HALO; k++) r[16 + k] = shdn1(r[k]);
    if ((tid & 31) == 31) {                // warp-boundary lanes load directly
        #pragma unroll
        for (int q = 0; q < 4; q++) {
            int ga = t0 + 16 + 4 * q, gb = ga + SEG;
            float va[4] = {SENT, SENT, SENT, SENT};
            float vb[4] = {SENT, SENT, SENT, SENT};
            if (ga + 3 < N_COLS) {
                float4 s4 = *reinterpret_cast<const float4*>(srow + ga);
                int4   m4 = *reinterpret_cast<const int4*>(mrow + ga);
                va[0] = m4.x == 0 ? SENT : s4.x; va[1] = m4.y == 0 ? SENT : s4.y;
                va[2] = m4.z == 0 ? SENT : s4.z; va[3] = m4.w == 0 ? SENT : s4.w;
            }
            if (gb + 3 < N_COLS) {
                float4 s4 = *reinterpret_cast<const float4*>(srow + gb);
                int4   m4 = *reinterpret_cast<const int4*>(mrow + gb);
                vb[0] = m4.x == 0 ? SENT : s4.x; vb[1] = m4.y == 0 ? SENT : s4.y;
                vb[2] = m4.z == 0 ? SENT : s4.z; vb[3] = m4.w == 0 ? SENT : s4.w;
            }
            #pragma unroll
            for (int c = 0; c < 4; c++) {
                int idx = 16 + 4 * q + c;
                if (idx < 30) r[idx] = __floats2half2_rn(va[c], vb[c]);
            }
        }
    }

    // ---- CTA-left halo: threads 0..13 compute start col0-14+tid (fp32) ----
    if (tid < HALO) {
        float hv[W_MAX];
        #pragma unroll
        for (int k = 0; k < W_MAX; k++) {
            int g = col0 - HALO + tid + k;
            float v = SENT;
            if (g >= 0) v = (mrow[g] == 0) ? SENT : srow[g];
            hv[k] = v;
        }
        float hw[NW];
        float m = fminf(hv[0], hv[1]);
        hw[0] = sww[0] * m;
        #pragma unroll
        for (int w = 3; w <= W_MAX; w++) {
            m = fminf(m, hv[w - 1]);
            hw[w - 2] = sww[w - 2] * m;
        }
        float g = hw[NW - 1];
        atomicMax(&xb[tid], fkey(g));      // d = 15 -> token tid
        #pragma unroll
        for (int d = W_MAX - 1; d >= 2; d--) {
            g = fmaxf(g, hw[d - 2]);
            int i = tid + d - W_MAX;
            if (i >= 0) atomicMax(&xb[i], fkey(g));
        }
    }

    // ---- 16 packed start-pairs, descending; streamed tail retirement ----
    __half2 boost[K_TOK + HALO];           // local slots 0..29 (x=segA, y=segB)
    #pragma unroll
    for (int jj = 0; jj < K_TOK; jj++) {
        const int j = K_TOK - 1 - jj;      // 15 .. 0
        __half2 h[NW];
        __half2 m = __hmin2(r[j], r[j + 1]);
        h[0] = __hmul2(m, ww2[0]);
        #pragma unroll
        for (int w = 3; w <= W_MAX; w++) {
            m = __hmin2(m, r[j + w - 1]);
            h[w - 2] = __hmul2(m, ww2[w - 2]);
        }
        __half2 g = h[NW - 1];                              // d = 15
        if (j == K_TOK - 1) boost[j + 14] = g;
        else                boost[j + 14] = __hmax2(boost[j + 14], g);
        #pragma unroll
        for (int d = W_MAX - 1; d >= 2; d--) {              // d = 14..2
            g = __hmax2(g, h[d - 2]);
            if (j == K_TOK - 1) boost[j + d - 1] = g;
            else                boost[j + d - 1] = __hmax2(boost[j + d - 1], g);
        }
        boost[j] = g;                                       // d = 1: first touch
        if (j >= 2) tailbuf[tid][j - 2] = boost[j + 14];    // retire slot j+14
    }
    __syncthreads();

    // ---- merge incoming tails into own slots 0..13 ----
    if (tid > 0) {
        #pragma unroll
        for (int k = 0; k < HALO; k++)
            boost[k] = __hmax2(boost[k], tailbuf[tid - 1][k]);
    } else {
        // segA head <- CTA-edge halo (xb); segB head <- thread 127's segA tail
        #pragma unroll
        for (int k = 0; k < HALO; k++) {
            __half2 inc = __floats2half2_rn(funkey(xb[k]),
                                            __low2float(tailbuf[TPB - 1][k]));
            boost[k] = __hmax2(boost[k], inc);
        }
    }

    // ---- epilogue: sentinel fixup + max(boost, masked) + axpy, fp32 ----
    const float gamma = *gamma_p;
    float* orow = out + (size_t)row * N_COLS;
    #pragma unroll
    for (int q = 0; q < 4; q++) {
        int ga = t0 + 4 * q, gb = ga + SEG;
        float4 sa = *reinterpret_cast<const float4*>(srow + ga);
        float4 sb = *reinterpret_cast<const float4*>(srow + gb);
        float4 oa, ob;
        #pragma unroll
        for (int c = 0; c < 4; c++) {
            int k = 4 * q + c;
            float bl = __low2float(boost[k]);
            float bh = __high2float(boost[k]);
            bl = (bl > -1000.f) ? bl : cfix;   // sentinel-class -> exact c
            bh = (bh > -1000.f) ? bh : cfix;
            float rl = __low2float(r[k]);
            float rh = __high2float(r[k]);
            float sA = (&sa.x)[c], sB = (&sb.x)[c];
            float fl = (rl == SENT) ? bl : fmaxf(bl, sA);  // max(boost, masked)
            float fh = (rh == SENT) ? bh : fmaxf(bh, sB);
            (&oa.x)[c] = sA + gamma * fl;
            (&ob.x)[c] = sB + gamma * fh;
        }
        *reinterpret_cast<float4*>(&orow[ga]) = oa;
        *reinterpret_cast<float4*>(&orow[gb]) = ob;
    }
}

extern "C" void kernel_launch(void* const* d_in, const int* in_sizes, int n_in,
                              void* d_out, int out_size)
{
    const float* scores = (const float*)d_in[0];
    const int*   mask   = (const int*)d_in[1];
    const float* gamma  = (const float*)d_in[2];
    const float* wlog   = (const float*)d_in[3];
    float* out = (float*)d_out;
    const int B = in_sizes[0] / N_COLS;   // 512
    dim3 grid(N_COLS / TILE, B);          // (2, 512)
    span_boost_kernel<<<grid, TPB>>>(scores, mask, gamma, wlog, out);
}

// round 11
// speedup vs baseline: 1.2088x; 1.0945x over previous
#include <cuda_runtime.h>
#include <cuda_fp16.h>

namespace {
constexpr int N_COLS = 8192;
constexpr int W_MAX  = 15;     // widths w = 2..15
constexpr int NW     = 14;
constexpr int HALO   = 14;     // W_MAX - 1
constexpr int TPB    = 128;    // 4 warps
constexpr int K_TOK  = 16;     // tokens per lane PER SEGMENT
constexpr int WTOK   = 32 * K_TOK;          // 512 tokens/warp/segment
constexpr int SEGOFF = N_COLS / 2;          // 4096: segment B offset
constexpr int CHUNK  = (TPB / 32) * WTOK;   // 2048 tokens/CTA/segment
constexpr float SENT = -60000.0f;           // fp16-exact sentinel
constexpr float NEGV = -1.0e9f;
constexpr unsigned FULL = 0xffffffffu;
}

__device__ __forceinline__ unsigned h2u(__half2 v) { return *reinterpret_cast<unsigned*>(&v); }
__device__ __forceinline__ __half2 u2h(unsigned u) { return *reinterpret_cast<__half2*>(&u); }

__global__ __launch_bounds__(TPB, 5) void span_boost_kernel(
    const float* __restrict__ scores,
    const int*   __restrict__ mask,
    const float* __restrict__ gamma_p,
    const float* __restrict__ wlog,
    float*       __restrict__ out)
{
    const float NINF = __int_as_float(0xff800000);
    const int tid  = threadIdx.x;
    const int lane = tid & 31;
    const int wid  = tid >> 5;
    const int row  = blockIdx.y;
    const float* srow = scores + (size_t)row * N_COLS;
    const int*   mrow = mask   + (size_t)row * N_COLS;

    const int wb = blockIdx.x * CHUNK + wid * WTOK;  // warp base (segment A)
    const int t0 = wb + lane * K_TOK;                // lane base (segment A)

    // ---- lane-parallel softmax: wwf[j] = weight of width j+2 (fp32) ----
    float wwf[NW];
    {
        float lg = (lane < W_MAX) ? __ldg(wlog + lane) : NINF;
        float mx = lg;
        #pragma unroll
        for (int o = 16; o >= 1; o >>= 1)
            mx = fmaxf(mx, __shfl_xor_sync(FULL, mx, o));
        float e = (lane < W_MAX) ? __expf(lg - mx) : 0.f;
        float s = e;
        #pragma unroll
        for (int o = 16; o >= 1; o >>= 1)
            s += __shfl_xor_sync(FULL, s, o);
        float wwv = __fdividef(e, s);
        #pragma unroll
        for (int j = 0; j < NW; j++)
            wwf[j] = __shfl_sync(FULL, wwv, j + 1);
    }
    float wmin = wwf[0];
    #pragma unroll
    for (int j = 1; j < NW; j++) wmin = fminf(wmin, wwf[j]);
    const float cfix = NEGV * wmin;        // exact sentinel-class boost value

    // ---- warp-left halo, BOTH segments in parallel (fp32, atomics-free) ----
    // lanes 0..13: segA halo starts wb-14+l;  lanes 16..29: segB halo.
    float acc = NINF;                      // halo boost for warp token l (per group)
    {
        const int l   = lane & 15;
        const bool act = (l < HALO);
        const int hb  = wb + ((lane >= 16) ? SEGOFF : 0);
        float hv[W_MAX];
        #pragma unroll
        for (int k = 0; k < W_MAX; k++) {
            int g = hb - HALO + l + k;
            float v = SENT;
            if (act && g >= 0) v = (mrow[g] == 0) ? SENT : srow[g];
            hv[k] = v;
        }
        float hw[NW];
        float m = fminf(hv[0], hv[1]);
        hw[0] = wwf[0] * m;
        #pragma unroll
        for (int w = 3; w <= W_MAX; w++) {
            m = fminf(m, hv[w - 1]);
            hw[w - 2] = wwf[w - 2] * m;
        }
        float Gv[16];                      // Gv[d] = max_{w>=d} hw
        Gv[15] = hw[13];
        #pragma unroll
        for (int d = 14; d >= 2; d--) Gv[d] = fmaxf(Gv[d + 1], hw[d - 2]);
        Gv[1] = Gv[2];
        #pragma unroll
        for (int k = 0; k < HALO; k++) {   // token l <- start l+k, depth 15-k
            float v = __shfl_down_sync(FULL, Gv[15 - k], k);
            if (act && l + k < HALO) acc = fmaxf(acc, v);
        }
    }

    // ---- packed masked values r[0..15] = {segA, segB} tokens ----
    __half2 r[30];
    #pragma unroll
    for (int q = 0; q < 4; q++) {
        int ga = t0 + 4 * q, gb = ga + SEGOFF;
        float4 sa = *reinterpret_cast<const float4*>(srow + ga);
        int4   ma = *reinterpret_cast<const int4*>(mrow + ga);
        float4 sb = *reinterpret_cast<const float4*>(srow + gb);
        int4   mb = *reinterpret_cast<const int4*>(mrow + gb);
        r[4*q+0] = __floats2half2_rn(ma.x == 0 ? SENT : sa.x, mb.x == 0 ? SENT : sb.x);
        r[4*q+1] = __floats2half2_rn(ma.y == 0 ? SENT : sa.y, mb.y == 0 ? SENT : sb.y);
        r[4*q+2] = __floats2half2_rn(ma.z == 0 ? SENT : sa.z, mb.z == 0 ? SENT : sb.z);
        r[4*q+3] = __floats2half2_rn(ma.w == 0 ? SENT : sa.w, mb.w == 0 ? SENT : sb.w);
    }
    // right halo r[16..29]: lane+1's r[0..13] (both halves at once)
    #pragma unroll
    for (int k = 0; k < HALO; k++)
        r[16 + k] = u2h(__shfl_down_sync(FULL, h2u(r[k]), 1));
    if (lane == 31) {                      // real right halo at warp boundary
        #pragma unroll
        for (int q = 0; q < 4; q++) {
            int ga = t0 + 16 + 4 * q, gb = ga + SEGOFF;
            float va[4] = {SENT, SENT, SENT, SENT};
            float vb[4] = {SENT, SENT, SENT, SENT};
            if (ga + 3 < N_COLS) {
                float4 s4 = *reinterpret_cast<const float4*>(srow + ga);
                int4   m4 = *reinterpret_cast<const int4*>(mrow + ga);
                va[0] = m4.x == 0 ? SENT : s4.x; va[1] = m4.y == 0 ? SENT : s4.y;
                va[2] = m4.z == 0 ? SENT : s4.z; va[3] = m4.w == 0 ? SENT : s4.w;
            }
            if (gb + 3 < N_COLS) {
                float4 s4 = *reinterpret_cast<const float4*>(srow + gb);
                int4   m4 = *reinterpret_cast<const int4*>(mrow + gb);
                vb[0] = m4.x == 0 ? SENT : s4.x; vb[1] = m4.y == 0 ? SENT : s4.y;
                vb[2] = m4.z == 0 ? SENT : s4.z; vb[3] = m4.w == 0 ? SENT : s4.w;
            }
            #pragma unroll
            for (int c = 0; c < 4; c++) {
                int idx = 16 + 4 * q + c;
                if (idx < 30) r[idx] = __floats2half2_rn(va[c], vb[c]);
            }
        }
    }

    // ---- packed weights (wwf dies here) ----
    __half2 ww2[NW];
    #pragma unroll
    for (int j = 0; j < NW; j++) ww2[j] = __float2half2_rn(wwf[j]);
    const __half2 SENT2 = __float2half2_rn(SENT);

    // ---- 16 packed starts, descending; streamed shuffle handoff ----
    __half2 boost[K_TOK + HALO];
    #pragma unroll
    for (int jj = 0; jj < K_TOK; jj++) {
        const int j = K_TOK - 1 - jj;      // 15 .. 0
        __half2 h[NW];
        __half2 m = __hmin2(r[j], r[j + 1]);
        h[0] = __hmul2(m, ww2[0]);
        #pragma unroll
        for (int w = 3; w <= W_MAX; w++) {
            m = __hmin2(m, r[j + w - 1]);
            h[w - 2] = __hmul2(m, ww2[w - 2]);
        }
        __half2 g = h[NW - 1];                              // d = 15
        if (j == K_TOK - 1) boost[j + 14] = g;
        else                boost[j + 14] = __hmax2(boost[j + 14], g);
        #pragma unroll
        for (int d = W_MAX - 1; d >= 2; d--) {              // d = 14..2
            g = __hmax2(g, h[d - 2]);
            if (j == K_TOK - 1) boost[j + d - 1] = g;
            else                boost[j + d - 1] = __hmax2(boost[j + d - 1], g);
        }
        if (j >= K_TOK - 2) boost[j] = g;                   // d = 1: first touch
        else                boost[j] = __hmax2(boost[j], g);
        if (j >= 2) {                                       // handoff slot j-2
            unsigned tin = __shfl_up_sync(FULL, h2u(boost[j + 14]), 1);
            boost[j - 2] = (lane == 0) ? SENT2 : u2h(tin);
        }
    }

    // ---- fold halo boosts into lane 0's slots 0..13 (both halves) ----
    #pragma unroll
    for (int i = 0; i < HALO; i++) {
        float vA = __shfl_sync(FULL, acc, i);
        float vB = __shfl_sync(FULL, acc, 16 + i);
        if (lane == 0)
            boost[i] = __hmax2(boost[i], __floats2half2_rn(vA, vB));
    }

    // ---- epilogue: sentinel fixup + max(boost, masked) + axpy (fp32) ----
    const float gamma = *gamma_p;
    float* orow = out + (size_t)row * N_COLS;
    #pragma unroll
    for (int q = 0; q < 4; q++) {
        int ga = t0 + 4 * q, gb = ga + SEGOFF;
        float4 sa = *reinterpret_cast<const float4*>(srow + ga);
        float4 sb = *reinterpret_cast<const float4*>(srow + gb);
        float4 oa, ob;
        #pragma unroll
        for (int c = 0; c < 4; c++) {
            int k = 4 * q + c;
            float bl = __low2float(boost[k]);
            float bh = __high2float(boost[k]);
            bl = (bl > -1000.f) ? bl : cfix;   // sentinel-class -> exact value
            bh = (bh > -1000.f) ? bh : cfix;
            float rl = __low2float(r[k]);
            float rh = __high2float(r[k]);
            float sA = (&sa.x)[c], sB = (&sb.x)[c];
            float fl = (rl == SENT) ? bl : fmaxf(bl, sA);
            float fh = (rh == SENT) ? bh : fmaxf(bh, sB);
            (&oa.x)[c] = sA + gamma * fl;
            (&ob.x)[c] = sB + gamma * fh;
        }
        *reinterpret_cast<float4*>(&orow[ga]) = oa;
        *reinterpret_cast<float4*>(&orow[gb]) = ob;
    }
}

extern "C" void kernel_launch(void* const* d_in, const int* in_sizes, int n_in,
                              void* d_out, int out_size)
{
    const float* scores = (const float*)d_in[0];
    const int*   mask   = (const int*)d_in[1];
    const float* gamma  = (const float*)d_in[2];
    const float* wlog   = (const float*)d_in[3];
    float* out = (float*)d_out;
    const int B = in_sizes[0] / N_COLS;   // 512
    dim3 grid(SEGOFF / CHUNK, B);         // (2, 512)
    span_boost_kernel<<<grid, TPB>>>(scores, mask, gamma, wlog, out);
}